// round 15
// baseline (speedup 1.0000x reference)
#include <cuda_runtime.h>
#include <cuda_bf16.h>
#include <cstdint>

typedef __nv_bfloat16 bf16;

#define BATCH 16
#define CH 512
#define HWN 4096
#define NHEADS 8
#define HD 64
#define MQKV (3 * CH)          // 1536 fused output rows for QKV

// ---- bf16 GEMM tiling (out-projection) ----
#define BM 128
#define BN 128
#define BK 32
#define SA 40
#define SB 136
#define NSTAGE 3
#define NIT (CH / BK)
#define AOFF (uint32_t)(BM * SA * 2)
#define BOFF (uint32_t)(BK * SB * 2)
#define SMEM_G (size_t)(NSTAGE * (2 * BM * SA + 2 * BK * SB) * 2)

// ---- int8 GEMM tiling (QKV projection) ----
#define SA8 48                     // bytes per 32B k-row (+16 pad), ldsm conflict-free
#define ASTG8 (uint32_t)(128 * SA8)   // 6144 bytes per stage per array
#define NIT8 (CH / 32)             // 16
#define SMEM_I8 (size_t)(NSTAGE * 4 * 128 * SA8)   // 73728

// ---------------------------------------------------------------------------
// Scratch (device globals — no allocation allowed)
// ---------------------------------------------------------------------------
__device__ float  g_kqv[(size_t)BATCH * MQKV * HWN];
__device__ float  g_ctx[BATCH * NHEADS * HD * HD];
__device__ int8_t g_x8h[(size_t)BATCH * HWN * CH];   // x quantized, K-major [b][n][c]
__device__ int8_t g_x8l[(size_t)BATCH * HWN * CH];
__device__ int8_t g_w8h[MQKV * CH];                  // stacked [Wk;Wq;Wv] quantized
__device__ int8_t g_w8l[MQKV * CH];
__device__ bf16   g_qh[(size_t)BATCH * CH * HWN];
__device__ bf16   g_ql[(size_t)BATCH * CH * HWN];
__device__ bf16   g_weffh[(size_t)BATCH * CH * CH];
__device__ bf16   g_weffl[(size_t)BATCH * CH * CH];

// ---------------------------------------------------------------------------
// PTX helpers
// ---------------------------------------------------------------------------
#define CP16(dst_u32, src_ptr) \
    asm volatile("cp.async.cg.shared.global [%0], [%1], 16;\n" :: "r"(dst_u32), "l"(src_ptr))
#define CP_COMMIT() asm volatile("cp.async.commit_group;\n" ::: "memory")
#define CP_WAIT1()  asm volatile("cp.async.wait_group 1;\n"  ::: "memory")

#define LDSM4(R, addr) \
    asm volatile("ldmatrix.sync.aligned.m8n8.x4.shared.b16 {%0,%1,%2,%3}, [%4];" \
        : "=r"((R)[0]), "=r"((R)[1]), "=r"((R)[2]), "=r"((R)[3]) : "r"(addr))

#define LDSM4T(R, addr) \
    asm volatile("ldmatrix.sync.aligned.m8n8.x4.trans.shared.b16 {%0,%1,%2,%3}, [%4];" \
        : "=r"((R)[0]), "=r"((R)[1]), "=r"((R)[2]), "=r"((R)[3]) : "r"(addr))

#define MMA16816(d, a, b0v, b1v) \
    asm volatile("mma.sync.aligned.m16n8k16.row.col.f32.bf16.bf16.f32 " \
        "{%0,%1,%2,%3},{%4,%5,%6,%7},{%8,%9},{%0,%1,%2,%3};" \
        : "+f"((d)[0]), "+f"((d)[1]), "+f"((d)[2]), "+f"((d)[3]) \
        : "r"((a)[0]), "r"((a)[1]), "r"((a)[2]), "r"((a)[3]), "r"(b0v), "r"(b1v))

#define IMMA16832(d, a, b0v, b1v) \
    asm volatile("mma.sync.aligned.m16n8k32.row.col.s32.s8.s8.s32 " \
        "{%0,%1,%2,%3},{%4,%5,%6,%7},{%8,%9},{%0,%1,%2,%3};" \
        : "+r"((d)[0]), "+r"((d)[1]), "+r"((d)[2]), "+r"((d)[3]) \
        : "r"((a)[0]), "r"((a)[1]), "r"((a)[2]), "r"((a)[3]), "r"(b0v), "r"(b1v))

__device__ __forceinline__ uint32_t smem_u32(const void* p) {
    uint32_t a;
    asm("{ .reg .u64 t; cvta.to.shared.u64 t, %1; cvt.u32.u64 %0, t; }" : "=r"(a) : "l"(p));
    return a;
}

__device__ __forceinline__ void split_f32(float v, bf16& h, bf16& l) {
    h = __float2bfloat16_rn(v);
    l = __float2bfloat16_rn(v - __bfloat162float(h));
}

// quantize to 16-bit fixed point, split v = h*256 + l, h/l in [-128,127]
__device__ __forceinline__ void q16_split(float x, float scale, int8_t& h, int8_t& l) {
    int v = (int)rintf(x * scale);
    v = min(max(v, -32768), 32639);
    int hh = (v + 128) >> 8;
    h = (int8_t)hh;
    l = (int8_t)(v - (hh << 8));
}

// ---------------------------------------------------------------------------
// int8 16-bit-fixed-point GEMM (QKV): out[b] = (W @ x[b]) + bias
// A (weights) s8 hi/lo [1536][512] row-major, batch-shared.
// B (x) s8 hi/lo K-major [b][4096][512].
// acc: hh (scale 2^16) and cross = Ah*Bl + Al*Bh (scale 2^8); ll dropped.
// out = (hh*65536 + cr*256) / 2^30 + bias   (S_w = 2^18, S_x = 2^12)
// ---------------------------------------------------------------------------
__global__ __launch_bounds__(256, 1) void gemm_i8(
    const int8_t* __restrict__ Ah, const int8_t* __restrict__ Al,
    const int8_t* __restrict__ Bh, const int8_t* __restrict__ Bl,
    const float* __restrict__ bias0, const float* __restrict__ bias1,
    const float* __restrict__ bias2,
    float* __restrict__ out)
{
    extern __shared__ __align__(16) int8_t dsm8[];
    const uint32_t sbase = smem_u32(dsm8);
    const uint32_t sAh = sbase;
    const uint32_t sAl = sbase + 3 * ASTG8;
    const uint32_t sBh = sbase + 6 * ASTG8;
    const uint32_t sBl = sbase + 9 * ASTG8;

    const int bz = blockIdx.z;
    const int m0 = blockIdx.y * BM;
    const int n0 = blockIdx.x * BN;
    const int8_t* Ahg = Ah + (long)m0 * CH;
    const int8_t* Alg = Al + (long)m0 * CH;
    const int8_t* Bhg = Bh + ((long)bz * HWN + n0) * CH;
    const int8_t* Blg = Bl + ((long)bz * HWN + n0) * CH;
    out += (long)bz * (long)MQKV * HWN;

    const int t = threadIdx.x, lane = t & 31, wid = t >> 5;
    const int wm = (wid >> 2) * 64;
    const int wn = (wid & 3) * 32;

    // staging: 1024 x 16B chunks: [0,256)=A-hi, [256,512)=A-lo, [512,768)=B-hi, [768,1024)=B-lo
#define STAGE8(st, k0) do {                                                          \
    _Pragma("unroll")                                                                \
    for (int c = 0; c < 4; c++) {                                                    \
        int idx = c * 256 + t;                                                       \
        int isB = idx >> 9, arr = (idx >> 8) & 1;                                    \
        int row = (idx >> 1) & 127, ch = idx & 1;                                    \
        uint32_t dst = (isB ? (arr ? sBl : sBh) : (arr ? sAl : sAh))                 \
                     + (uint32_t)(st) * ASTG8 + (uint32_t)(row * SA8 + ch * 16);     \
        const int8_t* src = (isB ? (arr ? Blg : Bhg) : (arr ? Alg : Ahg))            \
                          + (long)row * CH + (k0) + ch * 16;                         \
        CP16(dst, src);                                                              \
    } } while (0)

    int hh[4][4][4], cr[4][4][4];
#pragma unroll
    for (int i = 0; i < 4; i++)
#pragma unroll
        for (int j = 0; j < 4; j++)
#pragma unroll
            for (int r = 0; r < 4; r++) { hh[i][j][r] = 0; cr[i][j][r] = 0; }

    STAGE8(0, 0);
    CP_COMMIT();
    STAGE8(1, 32);
    CP_COMMIT();

    const int a_lm = (lane & 15) * SA8 + (lane >> 4) * 16;
    const int b_row = (lane & 7) + ((lane >> 4) & 1) * 8;
    const int b_ch  = ((lane >> 3) & 1) * 16;

    int st = 0;
    for (int it = 0; it < NIT8; ++it) {
        CP_WAIT1();
        __syncthreads();

        if (it + 2 < NIT8) {
            const int wst = (st + 2 >= NSTAGE) ? (st + 2 - NSTAGE) : (st + 2);
            STAGE8(wst, (it + 2) * 32);
        }
        CP_COMMIT();

        uint32_t ah[4][4], al[4][4], bh[2][4], bl[2][4];
#pragma unroll
        for (int mt = 0; mt < 4; mt++) {
            const uint32_t ao = st * ASTG8 + (uint32_t)((wm + mt * 16) * SA8 + a_lm);
            LDSM4(ah[mt], sAh + ao);
            LDSM4(al[mt], sAl + ao);
        }
#pragma unroll
        for (int gi = 0; gi < 2; gi++) {
            const uint32_t bo = st * ASTG8
                + (uint32_t)((wn + gi * 16 + b_row) * SA8 + b_ch);
            LDSM4(bh[gi], sBh + bo);
            LDSM4(bl[gi], sBl + bo);
        }

#pragma unroll
        for (int mt = 0; mt < 4; mt++)
#pragma unroll
            for (int nt = 0; nt < 4; nt++) {
                const int gi = nt >> 1, p = (nt & 1) * 2;
                IMMA16832(hh[mt][nt], ah[mt], bh[gi][p], bh[gi][p + 1]);
                IMMA16832(cr[mt][nt], ah[mt], bl[gi][p], bl[gi][p + 1]);
                IMMA16832(cr[mt][nt], al[mt], bh[gi][p], bh[gi][p + 1]);
            }
        st = (st + 1 >= NSTAGE) ? 0 : st + 1;
    }

    // epilogue: combine fixed-point terms, add bias, store fp32
    const float SC = 1.f / 1073741824.f;   // 2^-30 = 1/(S_w * S_x)
    const int gq = lane >> 2, tq = lane & 3;
#pragma unroll
    for (int mt = 0; mt < 4; mt++) {
        const int m = m0 + wm + mt * 16 + gq;
        const float* bs = (m < CH) ? bias0 : (m < 2 * CH) ? bias1 : bias2;
        const float b0v = bs[m & (CH - 1)], b1v = bs[(m + 8) & (CH - 1)];
#pragma unroll
        for (int nt = 0; nt < 4; nt++) {
            const int n = n0 + wn + nt * 8 + tq * 2;
            float2 v0, v1;
            v0.x = ((float)hh[mt][nt][0] * 65536.f + (float)cr[mt][nt][0] * 256.f) * SC + b0v;
            v0.y = ((float)hh[mt][nt][1] * 65536.f + (float)cr[mt][nt][1] * 256.f) * SC + b0v;
            v1.x = ((float)hh[mt][nt][2] * 65536.f + (float)cr[mt][nt][2] * 256.f) * SC + b1v;
            v1.y = ((float)hh[mt][nt][3] * 65536.f + (float)cr[mt][nt][3] * 256.f) * SC + b1v;
            *reinterpret_cast<float2*>(&out[(long)m * HWN + n]) = v0;
            *reinterpret_cast<float2*>(&out[(long)(m + 8) * HWN + n]) = v1;
        }
    }
#undef STAGE8
}

// ---------------------------------------------------------------------------
// bf16x3 batched GEMM with bias (out-projection) — unchanged from R13
// ---------------------------------------------------------------------------
__global__ __launch_bounds__(256, 1) void gemm_bf16x3(
    const bf16* __restrict__ Ah, const bf16* __restrict__ Al, long a_bstride,
    const bf16* __restrict__ Bh, const bf16* __restrict__ Bl,
    const float* __restrict__ bias0,
    long out_bstride, float* __restrict__ out)
{
    extern __shared__ __align__(16) bf16 dsm[];
    const uint32_t sbase = smem_u32(dsm);
    const uint32_t sAh_b = sbase;
    const uint32_t sAl_b = sbase + NSTAGE * AOFF;
    const uint32_t sBh_b = sbase + 2 * NSTAGE * AOFF;
    const uint32_t sBl_b = sbase + 2 * NSTAGE * AOFF + NSTAGE * BOFF;

    const int bz = blockIdx.z;
    const int m0 = blockIdx.y * BM;
    const int n0 = blockIdx.x * BN;
    const bf16* Ahg = Ah + (long)bz * a_bstride + (long)m0 * CH;
    const bf16* Alg = Al + (long)bz * a_bstride + (long)m0 * CH;
    const bf16* Bhg = Bh + (long)bz * (long)CH * HWN + n0;
    const bf16* Blg = Bl + (long)bz * (long)CH * HWN + n0;
    out += (long)bz * out_bstride;

    const int t = threadIdx.x, lane = t & 31, wid = t >> 5;
    const int wm = (wid >> 2) * 64;
    const int wn = (wid & 3) * 32;

#define STAGE_ISSUE(st, k0) do {                                                     \
    _Pragma("unroll")                                                                \
    for (int c = 0; c < 4; c++) {                                                    \
        int idx = c * 256 + t;                                                       \
        int arr = idx >> 9;                                                          \
        int a = idx & 511;                                                           \
        int row = a >> 2, kc = a & 3;                                                \
        uint32_t dst = (arr ? sAl_b : sAh_b) + (uint32_t)(st) * AOFF                 \
                     + (uint32_t)(row * SA + kc * 8) * 2;                            \
        const bf16* src = (arr ? Alg : Ahg) + (long)row * CH + (k0) + kc * 8;        \
        CP16(dst, src);                                                              \
    }                                                                                \
    _Pragma("unroll")                                                                \
    for (int c = 0; c < 4; c++) {                                                    \
        int idx = c * 256 + t;                                                       \
        int arr = idx >> 9;                                                          \
        int b2 = idx & 511;                                                          \
        int kr = b2 >> 4, nc = b2 & 15;                                              \
        uint32_t dst = (arr ? sBl_b : sBh_b) + (uint32_t)(st) * BOFF                 \
                     + (uint32_t)(kr * SB + nc * 8) * 2;                             \
        const bf16* src = (arr ? Blg : Bhg) + (long)((k0) + kr) * HWN + nc * 8;      \
        CP16(dst, src);                                                              \
    } } while (0)

    float acc[4][4][4];
#pragma unroll
    for (int i = 0; i < 4; i++)
#pragma unroll
        for (int j = 0; j < 4; j++)
#pragma unroll
            for (int r = 0; r < 4; r++) acc[i][j][r] = 0.f;

    STAGE_ISSUE(0, 0);
    CP_COMMIT();
    STAGE_ISSUE(1, BK);
    CP_COMMIT();

    const int a_row = lane & 15, a_colq = (lane >> 4) * 8;

    int st = 0;
    for (int it = 0; it < NIT; ++it) {
        CP_WAIT1();
        __syncthreads();

        if (it + 2 < NIT) {
            const int wst = (st + 2 >= NSTAGE) ? (st + 2 - NSTAGE) : (st + 2);
            STAGE_ISSUE(wst, (it + 2) * BK);
        }
        CP_COMMIT();

#pragma unroll
        for (int ks = 0; ks < 2; ks++) {
            uint32_t ah[4][4], al[4][4], bh[2][4], bl[2][4];
#pragma unroll
            for (int mt = 0; mt < 4; mt++) {
                const uint32_t ao = st * AOFF
                    + (uint32_t)((wm + mt * 16 + a_row) * SA + ks * 16 + a_colq) * 2;
                LDSM4(ah[mt], sAh_b + ao);
                LDSM4(al[mt], sAl_b + ao);
            }
#pragma unroll
            for (int gi = 0; gi < 2; gi++) {
                const uint32_t bo = st * BOFF
                    + (uint32_t)((ks * 16 + a_row) * SB + wn + gi * 16 + a_colq) * 2;
                LDSM4T(bh[gi], sBh_b + bo);
                LDSM4T(bl[gi], sBl_b + bo);
            }
#pragma unroll
            for (int mt = 0; mt < 4; mt++)
#pragma unroll
                for (int nt = 0; nt < 4; nt++) {
                    const int gi = nt >> 1, p = (nt & 1) * 2;
                    MMA16816(acc[mt][nt], ah[mt], bh[gi][p], bh[gi][p + 1]);
                    MMA16816(acc[mt][nt], ah[mt], bl[gi][p], bl[gi][p + 1]);
                    MMA16816(acc[mt][nt], al[mt], bh[gi][p], bh[gi][p + 1]);
                }
        }
        st = (st + 1 >= NSTAGE) ? 0 : st + 1;
    }

    const int gq = lane >> 2, tq = lane & 3;
#pragma unroll
    for (int mt = 0; mt < 4; mt++) {
        const int m = m0 + wm + mt * 16 + gq;
        const float b0v = bias0[m & (CH - 1)], b1v = bias0[(m + 8) & (CH - 1)];
#pragma unroll
        for (int nt = 0; nt < 4; nt++) {
            const int n = n0 + wn + nt * 8 + tq * 2;
            float2 v0 = make_float2(acc[mt][nt][0] + b0v, acc[mt][nt][1] + b0v);
            float2 v1 = make_float2(acc[mt][nt][2] + b1v, acc[mt][nt][3] + b1v);
            *reinterpret_cast<float2*>(&out[(long)m * HWN + n]) = v0;
            *reinterpret_cast<float2*>(&out[(long)(m + 8) * HWN + n]) = v1;
        }
    }
#undef STAGE_ISSUE
}

// ---------------------------------------------------------------------------
// Weight quantization: fp32 [n] -> s8 hi/lo, scale 2^18 (float4 per thread)
// ---------------------------------------------------------------------------
__global__ __launch_bounds__(256) void wquant(
    const float* __restrict__ in, int8_t* __restrict__ h8, int8_t* __restrict__ l8, int n4)
{
    const int i = blockIdx.x * 256 + threadIdx.x;
    if (i >= n4) return;
    float4 v = reinterpret_cast<const float4*>(in)[i];
    char4 hc, lc;
    q16_split(v.x, 262144.f, (int8_t&)hc.x, (int8_t&)lc.x);
    q16_split(v.y, 262144.f, (int8_t&)hc.y, (int8_t&)lc.y);
    q16_split(v.z, 262144.f, (int8_t&)hc.z, (int8_t&)lc.z);
    q16_split(v.w, 262144.f, (int8_t&)hc.w, (int8_t&)lc.w);
    reinterpret_cast<char4*>(h8)[i] = hc;
    reinterpret_cast<char4*>(l8)[i] = lc;
}

// ---------------------------------------------------------------------------
// x transpose + quantize: [b][512][4096] fp32 -> [b][4096][512] s8 hi/lo, scale 2^12
// ---------------------------------------------------------------------------
__global__ __launch_bounds__(256) void xpose_quant(
    const float* __restrict__ x, int8_t* __restrict__ th, int8_t* __restrict__ tl)
{
    __shared__ float tile[32][33];
    const int b = blockIdx.z;
    const int n0 = blockIdx.x * 32, c0 = blockIdx.y * 32;
    const int tx = threadIdx.x & 31, ty = threadIdx.x >> 5;   // 32 x 8

    const float* xp = x + ((long)b * CH + c0) * HWN + n0;
#pragma unroll
    for (int i = 0; i < 4; i++)
        tile[ty + 8 * i][tx] = xp[(long)(ty + 8 * i) * HWN + tx];
    __syncthreads();

    int8_t* hp = th + ((long)b * HWN + n0) * CH + c0;
    int8_t* lp = tl + ((long)b * HWN + n0) * CH + c0;
#pragma unroll
    for (int i = 0; i < 4; i++) {
        int8_t h, l;
        q16_split(tile[tx][ty + 8 * i], 4096.f, h, l);
        hp[(long)(ty + 8 * i) * CH + tx] = h;
        lp[(long)(ty + 8 * i) * CH + tx] = l;
    }
}

// ---------------------------------------------------------------------------
// Softmax over the spatial axis (4096) for the k section of g_kqv.
// ---------------------------------------------------------------------------
__global__ __launch_bounds__(256) void softmax_spatial()
{
    const int b = blockIdx.x >> 9;
    const int c = blockIdx.x & (CH - 1);
    float* p = g_kqv + ((long)b * MQKV + c) * HWN;
    const int t = threadIdx.x;

    __shared__ float redmax[8];
    __shared__ float redsum[8];

    float vals[16];
    float mx = -1e30f;
#pragma unroll
    for (int i = 0; i < 16; i++) {
        vals[i] = p[t + 256 * i];
        mx = fmaxf(mx, vals[i]);
    }
#pragma unroll
    for (int off = 16; off; off >>= 1)
        mx = fmaxf(mx, __shfl_xor_sync(0xffffffffu, mx, off));
    if ((t & 31) == 0) redmax[t >> 5] = mx;
    __syncthreads();
    float bm = redmax[0];
#pragma unroll
    for (int w = 1; w < 8; w++) bm = fmaxf(bm, redmax[w]);

    float s = 0.f;
#pragma unroll
    for (int i = 0; i < 16; i++) {
        vals[i] = __expf(vals[i] - bm);
        s += vals[i];
    }
#pragma unroll
    for (int off = 16; off; off >>= 1)
        s += __shfl_xor_sync(0xffffffffu, s, off);
    if ((t & 31) == 0) redsum[t >> 5] = s;
    __syncthreads();
    float tot = 0.f;
#pragma unroll
    for (int w = 0; w < 8; w++) tot += redsum[w];
    const float inv = 1.f / tot;

#pragma unroll
    for (int i = 0; i < 16; i++)
        p[t + 256 * i] = vals[i] * inv;
}

// ---------------------------------------------------------------------------
// Per-head channel softmax (64) for the q section; emits bf16 hi/lo split.
// ---------------------------------------------------------------------------
__global__ __launch_bounds__(256) void softmax_channel_split(
    bf16* __restrict__ qh, bf16* __restrict__ ql)
{
    const int idx = blockIdx.x * 256 + threadIdx.x;   // B * NHEADS * HWN
    const int l  = idx & (HWN - 1);
    const int bh = idx >> 12;
    const int h  = bh & (NHEADS - 1);
    const int b  = bh >> 3;
    const float* src = g_kqv + ((long)b * MQKV + CH + (long)h * HD) * HWN + l;
    const long dst = ((long)b * CH + (long)h * HD) * HWN + l;

    float v[HD];
    float mx = -1e30f;
#pragma unroll
    for (int c = 0; c < HD; c++) {
        v[c] = src[(long)c * HWN];
        mx = fmaxf(mx, v[c]);
    }
    float s = 0.f;
#pragma unroll
    for (int c = 0; c < HD; c++) {
        v[c] = __expf(v[c] - mx);
        s += v[c];
    }
    const float inv = 1.f / s;
#pragma unroll
    for (int c = 0; c < HD; c++) {
        bf16 hh, ll;
        split_f32(v[c] * inv, hh, ll);
        qh[dst + (long)c * HWN] = hh;
        ql[dst + (long)c * HWN] = ll;
    }
}

// ---------------------------------------------------------------------------
// ctx[b,h] = k_soft[b,h] @ v[b,h]^T : [64,4096] x [64,4096]^T -> [64,64]
// ---------------------------------------------------------------------------
__global__ __launch_bounds__(256) void ctx_kernel()
{
    const int bh = blockIdx.x;
    const int b = bh >> 3, h = bh & (NHEADS - 1);
    const float* kp = g_kqv + ((long)b * MQKV + (long)h * HD) * HWN;
    const float* vp = g_kqv + ((long)b * MQKV + 2 * CH + (long)h * HD) * HWN;

    __shared__ float ks[64][65];
    __shared__ float vs[64][65];

    const int t  = threadIdx.x;
    const int tx = t & 15, ty = t >> 4;
    float acc[4][4] = {};

    for (int l0 = 0; l0 < HWN; l0 += 64) {
#pragma unroll
        for (int r = 0; r < 16; r++) {
            const int idx = t + r * 256;
            const int row = idx >> 6, col = idx & 63;
            ks[row][col] = kp[(long)row * HWN + l0 + col];
            vs[row][col] = vp[(long)row * HWN + l0 + col];
        }
        __syncthreads();
#pragma unroll
        for (int ll = 0; ll < 64; ll++) {
            float a[4], bb[4];
#pragma unroll
            for (int i = 0; i < 4; i++) a[i] = ks[ty * 4 + i][ll];
#pragma unroll
            for (int j = 0; j < 4; j++) bb[j] = vs[tx * 4 + j][ll];
#pragma unroll
            for (int i = 0; i < 4; i++)
#pragma unroll
                for (int j = 0; j < 4; j++)
                    acc[i][j] += a[i] * bb[j];
        }
        __syncthreads();
    }

    float* cp = g_ctx + (long)bh * HD * HD;
#pragma unroll
    for (int i = 0; i < 4; i++)
#pragma unroll
        for (int j = 0; j < 4; j++)
            cp[(ty * 4 + i) * HD + tx * 4 + j] = acc[i][j];
}

// ---------------------------------------------------------------------------
// Weff[b][o][h*64+k] = sum_v Wr[o, h*64+v] * ctx[b,h,k,v] -> bf16 hi/lo
// ---------------------------------------------------------------------------
__global__ __launch_bounds__(256) void weff_split(const float* __restrict__ Wr)
{
    const int idx = blockIdx.x * 256 + threadIdx.x;
    const int col = idx & (CH - 1);
    const int o   = (idx >> 9) & (CH - 1);
    const int b   = idx >> 18;
    const int h   = col >> 6;
    const int kk  = col & 63;

    const float* wr = Wr + (long)o * CH + h * HD;
    const float* cx = g_ctx + ((long)(b * NHEADS + h) * HD + kk) * HD;
    float s = 0.f;
#pragma unroll
    for (int vv = 0; vv < HD; vv++)
        s += wr[vv] * cx[vv];
    bf16 hh, ll;
    split_f32(s, hh, ll);
    g_weffh[idx] = hh;
    g_weffl[idx] = ll;
}

// ---------------------------------------------------------------------------
extern "C" void kernel_launch(void* const* d_in, const int* in_sizes, int n_in,
                              void* d_out, int out_size)
{
    const float* x  = (const float*)d_in[0];
    const float* Wk = (const float*)d_in[1];
    const float* bk = (const float*)d_in[2];
    const float* Wq = (const float*)d_in[3];
    const float* bq = (const float*)d_in[4];
    const float* Wv = (const float*)d_in[5];
    const float* bv = (const float*)d_in[6];
    const float* Wr = (const float*)d_in[7];
    const float* br = (const float*)d_in[8];
    float* out = (float*)d_out;

    float* pkqv;
    int8_t *px8h, *px8l, *pw8h, *pw8l;
    bf16 *pqh, *pql, *pweh, *pwel;
    cudaGetSymbolAddress((void**)&pkqv, g_kqv);
    cudaGetSymbolAddress((void**)&px8h, g_x8h);
    cudaGetSymbolAddress((void**)&px8l, g_x8l);
    cudaGetSymbolAddress((void**)&pw8h, g_w8h);
    cudaGetSymbolAddress((void**)&pw8l, g_w8l);
    cudaGetSymbolAddress((void**)&pqh,  g_qh);
    cudaGetSymbolAddress((void**)&pql,  g_ql);
    cudaGetSymbolAddress((void**)&pweh, g_weffh);
    cudaGetSymbolAddress((void**)&pwel, g_weffl);

    cudaFuncSetAttribute(gemm_i8, cudaFuncAttributeMaxDynamicSharedMemorySize,
                         (int)SMEM_I8);
    cudaFuncSetAttribute(gemm_bf16x3, cudaFuncAttributeMaxDynamicSharedMemorySize,
                         (int)SMEM_G);

    const int WN4 = CH * CH / 4;

    // quantize weights (stacked [Wk;Wq;Wv]) and x (transposed, K-major)
    wquant<<<WN4 / 256, 256>>>(Wk, pw8h + 0 * CH * CH, pw8l + 0 * CH * CH, WN4);
    wquant<<<WN4 / 256, 256>>>(Wq, pw8h + 1 * CH * CH, pw8l + 1 * CH * CH, WN4);
    wquant<<<WN4 / 256, 256>>>(Wv, pw8h + 2 * CH * CH, pw8l + 2 * CH * CH, WN4);
    dim3 xg(HWN / 32, CH / 32, BATCH);
    xpose_quant<<<xg, 256>>>(x, px8h, px8l);

    // fused QKV projection on int8 tensor cores
    dim3 qkv_grid(HWN / BN, MQKV / BM, BATCH);
    gemm_i8<<<qkv_grid, 256, SMEM_I8>>>(pw8h, pw8l, px8h, px8l,
                                        bk, bq, bv, pkqv);

    // softmaxes
    softmax_spatial<<<BATCH * CH, 256>>>();
    softmax_channel_split<<<(BATCH * NHEADS * HWN) / 256, 256>>>(pqh, pql);

    // ctx = k @ v^T per (b, h)
    ctx_kernel<<<BATCH * NHEADS, 256>>>();

    // fold Wr through ctx -> per-batch effective weight (bf16 hi/lo)
    weff_split<<<(BATCH * CH * CH) / 256, 256>>>(Wr);

    // out[b] = Weff[b] @ q[b] + br (bf16x3 tensor cores)
    dim3 out_grid(HWN / BN, CH / BM, BATCH);
    gemm_bf16x3<<<out_grid, 256, SMEM_G>>>(pweh, pwel, (long)CH * CH, pqh, pql,
                                           br, (long)CH * HWN, out);
}